// round 2
// baseline (speedup 1.0000x reference)
#include <cuda_runtime.h>
#include <math.h>

#define BB   4
#define LL   2048
#define DD   2048
#define SS   16
#define KTOP 4
#define HH   32
#define HDH  64
#define HS   512
#define EPSR 1e-6f
#define ATT_SCALE 0.125f

__device__ __align__(128) float g_ws    [BB*SS*DD];
__device__ __align__(128) float g_cw    [SS*DD];
__device__ __align__(128) float g_logits[BB*SS*LL];
__device__ __align__(128) float g_xm    [BB*SS*DD];
__device__ __align__(128) float g_t     [BB*SS*DD];
__device__ __align__(128) float g_kv    [BB*SS*2*DD];
__device__ __align__(128) float g_m     [BB*HS*DD];
__device__ __align__(128) float g_p     [BB*HS*DD];
__device__ __align__(128) float g_c     [BB*HS];
__device__ __align__(128) float g_att   [(size_t)BB*LL*HS];
__device__ __align__(128) float g_y     [(size_t)BB*LL*DD];
__device__ __align__(128) float g_rs    [BB*LL];

__device__ __forceinline__ float blk_sum256(float v, float* sb)
{
    #pragma unroll
    for (int o = 16; o > 0; o >>= 1) v += __shfl_down_sync(0xffffffffu, v, o);
    if ((threadIdx.x & 31) == 0) sb[threadIdx.x >> 5] = v;
    __syncthreads();
    if (threadIdx.x == 0) {
        float t = 0.f;
        #pragma unroll
        for (int i = 0; i < 8; ++i) t += sb[i];
        sb[8] = t;
    }
    __syncthreads();
    float r = sb[8];
    __syncthreads();
    return r;
}

// copy x -> xbuf, compute pre-norm rsqrt per row
__global__ __launch_bounds__(256) void k_init_x(const float* __restrict__ xin,
                                                float* __restrict__ xout)
{
    __shared__ float sb[9];
    size_t row = blockIdx.x;
    const float* ir = xin + row * DD;
    float* orow = xout + row * DD;
    float ss = 0.f;
    #pragma unroll
    for (int i = 0; i < 8; ++i) {
        float v = ir[threadIdx.x + i * 256];
        orow[threadIdx.x + i * 256] = v;
        ss += v * v;
    }
    ss = blk_sum256(ss, sb);
    if (threadIdx.x == 0) g_rs[row] = rsqrtf(ss * (1.0f / DD) + EPSR);
}

__global__ __launch_bounds__(256) void k_init_ws(const float* __restrict__ wsrc)
{
    int i = blockIdx.x * 256 + threadIdx.x;
    g_ws[i] = wsrc[i & (SS * DD - 1)];
}

__global__ __launch_bounds__(256) void k_cw(const float* __restrict__ cw,
                                            const float* __restrict__ npw)
{
    int i = blockIdx.x * 256 + threadIdx.x;
    g_cw[i] = cw[i] * npw[i & (DD - 1)];
}

// logits transposed to (b,s,l): rs[row]*(x.cw') + cb[s]
__global__ __launch_bounds__(256) void k_compete(const float* __restrict__ x,
                                                 const float* __restrict__ cb)
{
    __shared__ float Xs[32][128];
    __shared__ float Cs[32][16];
    int m0 = blockIdx.x * 128;
    int tid = threadIdx.x;
    int col = tid & 15, ty = tid >> 4;
    float acc[8] = {0,0,0,0,0,0,0,0};
    for (int kt = 0; kt < DD; kt += 32) {
        #pragma unroll
        for (int it = 0; it < 4; ++it) {
            int idx = it * 256 + tid;
            int r = idx >> 3; int q = (idx & 7) * 4;
            float4 a = *(const float4*)(x + (size_t)(m0 + r) * DD + kt + q);
            Xs[q+0][r] = a.x; Xs[q+1][r] = a.y; Xs[q+2][r] = a.z; Xs[q+3][r] = a.w;
        }
        if (tid < 128) {
            int s = tid >> 3; int q = (tid & 7) * 4;
            float4 c = *(const float4*)(g_cw + (size_t)s * DD + kt + q);
            Cs[q+0][s] = c.x; Cs[q+1][s] = c.y; Cs[q+2][s] = c.z; Cs[q+3][s] = c.w;
        }
        __syncthreads();
        #pragma unroll
        for (int k = 0; k < 32; ++k) {
            float c = Cs[k][col];
            #pragma unroll
            for (int i = 0; i < 8; ++i) acc[i] += Xs[k][ty * 8 + i] * c;
        }
        __syncthreads();
    }
    #pragma unroll
    for (int i = 0; i < 8; ++i) {
        int row = m0 + ty * 8 + i;
        int b = row >> 11; int l = row & (LL - 1);
        g_logits[((size_t)(b * SS + col)) * LL + l] = acc[i] * g_rs[row] + cb[col];
    }
}

// top-4 (value desc, index asc), softmax, weighted gather of x rows
__global__ __launch_bounds__(256) void k_topk_xm(const float* __restrict__ x)
{
    __shared__ float sv[LL];
    __shared__ float rv[256];
    __shared__ int   ri[256];
    __shared__ float topv[KTOP];
    __shared__ int   topi[KTOP];
    __shared__ float wgt[KTOP];
    int r = blockIdx.x;
    int b = r >> 4;
    int tid = threadIdx.x;
    for (int i = tid; i < LL; i += 256) sv[i] = g_logits[(size_t)r * LL + i];
    __syncthreads();
    for (int k = 0; k < KTOP; ++k) {
        float bv = -INFINITY; int bi = 0x7fffffff;
        for (int i = tid; i < LL; i += 256) {
            float v = sv[i];
            if (v > bv || (v == bv && i < bi)) { bv = v; bi = i; }
        }
        rv[tid] = bv; ri[tid] = bi;
        __syncthreads();
        for (int off = 128; off > 0; off >>= 1) {
            if (tid < off) {
                float v2 = rv[tid + off]; int i2 = ri[tid + off];
                if (v2 > rv[tid] || (v2 == rv[tid] && i2 < ri[tid])) { rv[tid] = v2; ri[tid] = i2; }
            }
            __syncthreads();
        }
        if (tid == 0) { topv[k] = rv[0]; topi[k] = ri[0]; sv[ri[0]] = -INFINITY; }
        __syncthreads();
    }
    if (tid == 0) {
        float m = topv[0];
        float e[KTOP]; float ssum = 0.f;
        #pragma unroll
        for (int k = 0; k < KTOP; ++k) { e[k] = expf(topv[k] - m); ssum += e[k]; }
        #pragma unroll
        for (int k = 0; k < KTOP; ++k) wgt[k] = e[k] / ssum;
    }
    __syncthreads();
    float w0 = wgt[0], w1 = wgt[1], w2 = wgt[2], w3 = wgt[3];
    const float* x0 = x + ((size_t)b * LL + topi[0]) * DD;
    const float* x1 = x + ((size_t)b * LL + topi[1]) * DD;
    const float* x2 = x + ((size_t)b * LL + topi[2]) * DD;
    const float* x3 = x + ((size_t)b * LL + topi[3]) * DD;
    float* xo = g_xm + (size_t)r * DD;
    for (int d = tid; d < DD; d += 256)
        xo[d] = w0 * x0[d] + w1 * x1[d] + w2 * x2[d] + w3 * x3[d];
}

// small GEMM: out[r][n] = bias[n] + (res? res[r*Nout+n]:0) + sum_k A[r][k]*W[n][k]
// M = 64 rows fixed, K = DD, deterministic (no atomics).
__global__ __launch_bounds__(256) void k_sg(const float* __restrict__ A,
                                            const float* __restrict__ W,
                                            const float* __restrict__ bias,
                                            const float* __restrict__ res,
                                            float* __restrict__ out, int Nout)
{
    const int n0 = blockIdx.x * 64;
    __shared__ float As[32][64];
    __shared__ float Ws[32][64];
    int tid = threadIdx.x;
    int tx = tid & 15, ty = tid >> 4;
    float acc[4][4] = {};
    for (int kc = 0; kc < DD; kc += 32) {
        #pragma unroll
        for (int it = 0; it < 2; ++it) {
            int idx = it * 256 + tid;
            int r = idx >> 3; int q = (idx & 7) * 4;
            float4 a = *(const float4*)(A + (size_t)r * DD + kc + q);
            As[q+0][r] = a.x; As[q+1][r] = a.y; As[q+2][r] = a.z; As[q+3][r] = a.w;
            float4 w = *(const float4*)(W + (size_t)(n0 + r) * DD + kc + q);
            Ws[q+0][r] = w.x; Ws[q+1][r] = w.y; Ws[q+2][r] = w.z; Ws[q+3][r] = w.w;
        }
        __syncthreads();
        #pragma unroll
        for (int k = 0; k < 32; ++k) {
            float a[4], b[4];
            #pragma unroll
            for (int i = 0; i < 4; ++i) a[i] = As[k][ty * 4 + i];
            #pragma unroll
            for (int j = 0; j < 4; ++j) b[j] = Ws[k][tx * 4 + j];
            #pragma unroll
            for (int i = 0; i < 4; ++i)
                #pragma unroll
                for (int j = 0; j < 4; ++j) acc[i][j] += a[i] * b[j];
        }
        __syncthreads();
    }
    #pragma unroll
    for (int i = 0; i < 4; ++i) {
        int r = ty * 4 + i;
        #pragma unroll
        for (int j = 0; j < 4; ++j) {
            int n = n0 + tx * 4 + j;
            float v = bias[n] + acc[i][j];
            if (res) v += res[(size_t)r * Nout + n];
            out[(size_t)r * Nout + n] = v;
        }
    }
}

// row rms. WHICH=0: g_t->g_ws. WHICH=1: g_y->xout (+next-block g_rs)
template <int WHICH>
__global__ __launch_bounds__(256) void k_rmsn(float* __restrict__ xout,
                                              const float* __restrict__ w)
{
    __shared__ float sb[9];
    const float* in  = (WHICH == 0) ? g_t  : g_y;
    float*       out = (WHICH == 0) ? g_ws : xout;
    size_t row = blockIdx.x;
    const float* ir = in + row * DD;
    float v[8]; float ss = 0.f;
    #pragma unroll
    for (int i = 0; i < 8; ++i) { v[i] = ir[threadIdx.x + i * 256]; ss += v[i] * v[i]; }
    ss = blk_sum256(ss, sb);
    float rs = rsqrtf(ss * (1.0f / DD) + EPSR);
    float* orow = out + row * DD;
    float ss2 = 0.f;
    #pragma unroll
    for (int i = 0; i < 8; ++i) {
        float o = v[i] * rs * w[threadIdx.x + i * 256];
        orow[threadIdx.x + i * 256] = o;
        ss2 += o * o;
    }
    if (WHICH == 1) {
        ss2 = blk_sum256(ss2, sb);
        if (threadIdx.x == 0) g_rs[row] = rsqrtf(ss2 * (1.0f / DD) + EPSR);
    }
}

// c[b, h*16+s] = bq_head . kk_head
__global__ __launch_bounds__(256) void k_c(const float* __restrict__ ipb)
{
    int o = blockIdx.x * 256 + threadIdx.x;   // < BB*HH*SS
    int b = o / (HH * SS);
    int h = (o / SS) % HH;
    int s = o % SS;
    const float* kkrow = g_kv + ((size_t)(b * SS + s)) * (2 * DD);
    float acc = 0.f;
    #pragma unroll 8
    for (int j = 0; j < HDH; ++j) acc += ipb[h * HDH + j] * kkrow[h * HDH + j];
    g_c[(size_t)b * HS + h * SS + s] = acc;
}

// M[b, h*16+s, n] = sum_j kk[b,s,h*64+j] * wq[h*64+j][n]
__global__ __launch_bounds__(256) void k_m(const float* __restrict__ wq)
{
    int h = blockIdx.y; int n0 = blockIdx.x * 64;
    __shared__ float As[64][68];
    __shared__ float Bs[64][68];
    int tid = threadIdx.x;
    #pragma unroll
    for (int it = 0; it < 4; ++it) {
        int idx = it * 256 + tid;
        int r = idx >> 4; int q = (idx & 15) * 4;
        float4 a = *(const float4*)(g_kv + (size_t)r * (2 * DD) + h * HDH + q);
        *(float4*)(&As[r][q]) = a;
        float4 w = *(const float4*)(wq + (size_t)(h * HDH + r) * DD + n0 + q);
        *(float4*)(&Bs[r][q]) = w;
    }
    __syncthreads();
    int tx = tid & 15, ty = tid >> 4;
    float acc[4][4] = {};
    #pragma unroll 4
    for (int j = 0; j < 64; ++j) {
        float a[4], b[4];
        #pragma unroll
        for (int i = 0; i < 4; ++i) a[i] = As[ty * 4 + i][j];
        *(float4*)b = *(const float4*)(&Bs[j][tx * 4]);
        #pragma unroll
        for (int i = 0; i < 4; ++i)
            #pragma unroll
            for (int jj = 0; jj < 4; ++jj) acc[i][jj] += a[i] * b[jj];
    }
    #pragma unroll
    for (int i = 0; i < 4; ++i) {
        int r = ty * 4 + i; int b = r >> 4; int s = r & 15;
        float* o = g_m + ((size_t)b * HS + h * SS + s) * DD + n0 + tx * 4;
        *(float4*)o = *(float4*)(acc[i]);
    }
}

// P[b, h*16+s, n] = sum_j vv[b,s,h*64+j] * opw[n][h*64+j]
__global__ __launch_bounds__(256) void k_p(const float* __restrict__ Ow)
{
    int h = blockIdx.y; int n0 = blockIdx.x * 64;
    __shared__ float As[64][68];
    __shared__ float Bs[64][68];
    int tid = threadIdx.x;
    #pragma unroll
    for (int it = 0; it < 4; ++it) {
        int idx = it * 256 + tid;
        int r = idx >> 4; int q = (idx & 15) * 4;
        float4 a = *(const float4*)(g_kv + (size_t)r * (2 * DD) + DD + h * HDH + q);
        *(float4*)(&As[r][q]) = a;
        float4 w = *(const float4*)(Ow + (size_t)(n0 + r) * DD + h * HDH + q);
        Bs[q+0][r] = w.x; Bs[q+1][r] = w.y; Bs[q+2][r] = w.z; Bs[q+3][r] = w.w;
    }
    __syncthreads();
    int tx = tid & 15, ty = tid >> 4;
    float acc[4][4] = {};
    #pragma unroll 4
    for (int j = 0; j < 64; ++j) {
        float a[4], b[4];
        #pragma unroll
        for (int i = 0; i < 4; ++i) a[i] = As[ty * 4 + i][j];
        *(float4*)b = *(const float4*)(&Bs[j][tx * 4]);
        #pragma unroll
        for (int i = 0; i < 4; ++i)
            #pragma unroll
            for (int jj = 0; jj < 4; ++jj) acc[i][jj] += a[i] * b[jj];
    }
    #pragma unroll
    for (int i = 0; i < 4; ++i) {
        int r = ty * 4 + i; int b = r >> 4; int s = r & 15;
        float* o = g_p + ((size_t)b * HS + h * SS + s) * DD + n0 + tx * 4;
        *(float4*)o = *(float4*)(acc[i]);
    }
}

// E1: att[b,l,hs] = softmax_s( (x[b,l].M[b,hs] + c[b,hs]) * scale )
__global__ __launch_bounds__(256) void k_e1(const float* __restrict__ x)
{
    int b = blockIdx.z; int m0 = blockIdx.x * 128; int n0 = blockIdx.y * 128;
    const float* Ag = x   + ((size_t)b * LL + m0) * DD;
    const float* Bg = g_m + ((size_t)b * HS + n0) * DD;
    __shared__ float As[16][128];
    __shared__ float Bs[16][128];
    int tid = threadIdx.x; int tx = tid & 15, ty = tid >> 4;
    float acc[8][8] = {};
    for (int kt = 0; kt < DD; kt += 16) {
        #pragma unroll
        for (int it = 0; it < 2; ++it) {
            int idx = it * 256 + tid;
            int r = idx >> 2; int q = (idx & 3) * 4;
            float4 a = *(const float4*)(Ag + (size_t)r * DD + kt + q);
            As[q+0][r] = a.x; As[q+1][r] = a.y; As[q+2][r] = a.z; As[q+3][r] = a.w;
            float4 bb = *(const float4*)(Bg + (size_t)r * DD + kt + q);
            Bs[q+0][r] = bb.x; Bs[q+1][r] = bb.y; Bs[q+2][r] = bb.z; Bs[q+3][r] = bb.w;
        }
        __syncthreads();
        #pragma unroll
        for (int k = 0; k < 16; ++k) {
            float a[8], bv[8];
            *(float4*)(a)      = *(const float4*)(&As[k][ty * 8]);
            *(float4*)(a + 4)  = *(const float4*)(&As[k][ty * 8 + 4]);
            *(float4*)(bv)     = *(const float4*)(&Bs[k][tx * 8]);
            *(float4*)(bv + 4) = *(const float4*)(&Bs[k][tx * 8 + 4]);
            #pragma unroll
            for (int i = 0; i < 8; ++i)
                #pragma unroll
                for (int j = 0; j < 8; ++j) acc[i][j] += a[i] * bv[j];
        }
        __syncthreads();
    }
    float cv[8];
    #pragma unroll
    for (int j = 0; j < 8; ++j) cv[j] = g_c[(size_t)b * HS + n0 + tx * 8 + j];
    float* Og = g_att + ((size_t)b * LL + m0) * HS + n0;
    #pragma unroll
    for (int i = 0; i < 8; ++i) {
        float v[8]; float mx = -INFINITY;
        #pragma unroll
        for (int j = 0; j < 8; ++j) { v[j] = (acc[i][j] + cv[j]) * ATT_SCALE; mx = fmaxf(mx, v[j]); }
        float om = __shfl_xor_sync(0xffffffffu, mx, 1);
        mx = fmaxf(mx, om);
        float sm = 0.f;
        #pragma unroll
        for (int j = 0; j < 8; ++j) { v[j] = expf(v[j] - mx); sm += v[j]; }
        float os = __shfl_xor_sync(0xffffffffu, sm, 1);
        float inv = 1.0f / (sm + os);
        #pragma unroll
        for (int j = 0; j < 8; ++j) v[j] *= inv;
        float* orow = Og + (size_t)(ty * 8 + i) * HS + tx * 8;
        *(float4*)orow       = *(float4*)v;
        *(float4*)(orow + 4) = *(float4*)(v + 4);
    }
}

// E2: y[b,l,d] = x[b,l,d] + ob[d] + sum_hs att[b,l,hs] * P[b,hs,d]
__global__ __launch_bounds__(256) void k_e2(const float* __restrict__ x,
                                            const float* __restrict__ ob)
{
    int b = blockIdx.z; int m0 = blockIdx.x * 128; int n0 = blockIdx.y * 128;
    const float* Ag = g_att + ((size_t)b * LL + m0) * HS;
    const float* Bg = g_p   + (size_t)b * HS * DD;
    __shared__ float As[16][128];
    __shared__ float Bs[16][128];
    int tid = threadIdx.x; int tx = tid & 15, ty = tid >> 4;
    float acc[8][8] = {};
    for (int kt = 0; kt < HS; kt += 16) {
        #pragma unroll
        for (int it = 0; it < 2; ++it) {
            int idx = it * 256 + tid;
            int r = idx >> 2; int q = (idx & 3) * 4;
            float4 a = *(const float4*)(Ag + (size_t)r * HS + kt + q);
            As[q+0][r] = a.x; As[q+1][r] = a.y; As[q+2][r] = a.z; As[q+3][r] = a.w;
            int rk = idx >> 5; int c = (idx & 31) * 4;
            float4 bb = *(const float4*)(Bg + (size_t)(kt + rk) * DD + n0 + c);
            *(float4*)(&Bs[rk][c]) = bb;
        }
        __syncthreads();
        #pragma unroll
        for (int k = 0; k < 16; ++k) {
            float a[8], bv[8];
            *(float4*)(a)      = *(const float4*)(&As[k][ty * 8]);
            *(float4*)(a + 4)  = *(const float4*)(&As[k][ty * 8 + 4]);
            *(float4*)(bv)     = *(const float4*)(&Bs[k][tx * 8]);
            *(float4*)(bv + 4) = *(const float4*)(&Bs[k][tx * 8 + 4]);
            #pragma unroll
            for (int i = 0; i < 8; ++i)
                #pragma unroll
                for (int j = 0; j < 8; ++j) acc[i][j] += a[i] * bv[j];
        }
        __syncthreads();
    }
    #pragma unroll
    for (int i = 0; i < 8; ++i) {
        size_t row = (size_t)b * LL + m0 + ty * 8 + i;
        const float* xr = x + row * DD + n0 + tx * 8;
        float* yr = g_y + row * DD + n0 + tx * 8;
        #pragma unroll
        for (int j = 0; j < 8; ++j)
            yr[j] = xr[j] + ob[n0 + tx * 8 + j] + acc[i][j];
    }
}

extern "C" void kernel_launch(void* const* d_in, const int* in_sizes, int n_in,
                              void* d_out, int out_size)
{
    const float* x_in = (const float*)d_in[0];
    const float* ws_in= (const float*)d_in[1];
    const float* cw   = (const float*)d_in[2];
    const float* cb   = (const float*)d_in[3];
    const float* ww   = (const float*)d_in[4];
    const float* wb   = (const float*)d_in[5];
    const float* ipw  = (const float*)d_in[6];
    const float* ipb  = (const float*)d_in[7];
    const float* opw  = (const float*)d_in[8];
    const float* opb  = (const float*)d_in[9];
    const float* npw  = (const float*)d_in[12];   // norm_pre_w
    const float* npow = (const float*)d_in[13];   // norm_post_w
    float* xbuf = (float*)d_out;

    float *p_ws, *p_xm, *p_t, *p_kv;
    cudaGetSymbolAddress((void**)&p_ws, g_ws);
    cudaGetSymbolAddress((void**)&p_xm, g_xm);
    cudaGetSymbolAddress((void**)&p_t,  g_t);
    cudaGetSymbolAddress((void**)&p_kv, g_kv);

    k_init_x<<<BB*LL, 256>>>(x_in, xbuf);
    k_init_ws<<<BB*SS*DD/256, 256>>>(ws_in);
    k_cw<<<SS*DD/256, 256>>>(cw, npw);

    for (int blk = 0; blk < 2; ++blk) {
        k_compete<<<BB*LL/128, 256>>>(xbuf, cb);
        k_topk_xm<<<BB*SS, 256>>>(xbuf);
        // g_t = g_ws + wb + g_xm @ ww^T
        k_sg<<<DD/64, 256>>>(p_xm, ww, wb, p_ws, p_t, DD);
        k_rmsn<0><<<BB*SS, 256>>>(xbuf, npow);      // g_ws = rms(g_t)
        // g_kv = ipb[D..3D] + g_ws @ [wk;wv]^T
        k_sg<<<2*DD/64, 256>>>(p_ws, ipw + (size_t)DD*DD, ipb + DD, nullptr, p_kv, 2*DD);
        k_c<<<BB*HH*SS/256, 256>>>(ipb);
        k_m<<<dim3(DD/64, HH), 256>>>(ipw);
        k_p<<<dim3(DD/64, HH), 256>>>(opw);
        k_e1<<<dim3(LL/128, HS/128, BB), 256>>>(xbuf);
        k_e2<<<dim3(LL/128, DD/128, BB), 256>>>(xbuf, opb);
        k_rmsn<1><<<BB*LL, 256>>>(xbuf, npow);      // xbuf = rms(g_y), g_rs for next blk
    }
}

// round 4
// speedup vs baseline: 1.8622x; 1.8622x over previous
#include <cuda_runtime.h>
#include <cuda_bf16.h>
#include <math.h>
#include <stdint.h>

#define BB   4
#define LL   2048
#define DD   2048
#define SS   16
#define KTOP 4
#define HH   32
#define HDH  64
#define HS   512
#define EPSR 1e-6f
#define ATT_SCALE 0.125f

// fp32 scratch
__device__ __align__(128) float g_ws    [BB*SS*DD];
__device__ __align__(128) float g_cw    [SS*DD];
__device__ __align__(128) float g_logits[BB*SS*LL];
__device__ __align__(128) float g_xm    [BB*SS*DD];
__device__ __align__(128) float g_t     [BB*SS*DD];
__device__ __align__(128) float g_kv    [BB*SS*2*DD];
__device__ __align__(128) float g_c     [BB*HS];
__device__ __align__(128) float g_y     [(size_t)BB*LL*DD];
__device__ __align__(128) float g_rs    [BB*LL];
// bf16 split operands for tensor-core GEMMs
__device__ __align__(128) __nv_bfloat16 g_x_hi [(size_t)BB*LL*DD];
__device__ __align__(128) __nv_bfloat16 g_x_lo [(size_t)BB*LL*DD];
__device__ __align__(128) __nv_bfloat16 g_m_hi [(size_t)BB*HS*DD];
__device__ __align__(128) __nv_bfloat16 g_m_lo [(size_t)BB*HS*DD];
__device__ __align__(128) __nv_bfloat16 g_p_hi [(size_t)BB*DD*HS];   // [b][d][hs]
__device__ __align__(128) __nv_bfloat16 g_p_lo [(size_t)BB*DD*HS];
__device__ __align__(128) __nv_bfloat16 g_att_hi[(size_t)BB*LL*HS];
__device__ __align__(128) __nv_bfloat16 g_att_lo[(size_t)BB*LL*HS];

// ---------------- helpers ----------------
__device__ __forceinline__ uint32_t smem_u32(const void* p) {
    uint32_t a;
    asm("{ .reg .u64 t; cvta.to.shared.u64 t, %1; cvt.u32.u64 %0, t; }" : "=r"(a) : "l"(p));
    return a;
}

__device__ __forceinline__ void split2(float v, __nv_bfloat16& h, __nv_bfloat16& l) {
    h = __float2bfloat16_rn(v);
    l = __float2bfloat16_rn(v - __bfloat162float(h));
}

__device__ __forceinline__ float blk_sum256(float v, float* sb)
{
    #pragma unroll
    for (int o = 16; o > 0; o >>= 1) v += __shfl_down_sync(0xffffffffu, v, o);
    if ((threadIdx.x & 31) == 0) sb[threadIdx.x >> 5] = v;
    __syncthreads();
    if (threadIdx.x == 0) {
        float t = 0.f;
        #pragma unroll
        for (int i = 0; i < 8; ++i) t += sb[i];
        sb[8] = t;
    }
    __syncthreads();
    float r = sb[8];
    __syncthreads();
    return r;
}

__device__ __forceinline__ void mma16816(float* c, const uint32_t* a, const uint32_t* b) {
    asm volatile("mma.sync.aligned.m16n8k16.row.col.f32.bf16.bf16.f32 "
        "{%0,%1,%2,%3},{%4,%5,%6,%7},{%8,%9},{%0,%1,%2,%3};"
        : "+f"(c[0]), "+f"(c[1]), "+f"(c[2]), "+f"(c[3])
        : "r"(a[0]), "r"(a[1]), "r"(a[2]), "r"(a[3]), "r"(b[0]), "r"(b[1]));
}

// swizzled LDS.32 from a [rows][32 bf16] tile (64B rows, chunk xor (row>>1)&3)
__device__ __forceinline__ uint32_t lds32(uint32_t base, int row, int word) {
    int chunk = word >> 2, w = word & 3;
    uint32_t addr = base + row * 64 + (((chunk ^ ((row >> 1) & 3)) << 4) | (w << 2));
    uint32_t v;
    asm volatile("ld.shared.b32 %0, [%1];" : "=r"(v) : "r"(addr));
    return v;
}

__device__ __forceinline__ void cpasync16(uint32_t dst, const void* src) {
    asm volatile("cp.async.cg.shared.global [%0], [%1], 16;" :: "r"(dst), "l"(src) : "memory");
}

// ---------------- small kernels ----------------
__global__ __launch_bounds__(256) void k_init_x(const float* __restrict__ xin,
                                                float* __restrict__ xout)
{
    __shared__ float sb[9];
    size_t row = blockIdx.x;
    const float* ir = xin + row * DD;
    float* orow = xout + row * DD;
    float ss = 0.f;
    #pragma unroll
    for (int i = 0; i < 8; ++i) {
        int c = threadIdx.x + i * 256;
        float v = ir[c];
        orow[c] = v;
        __nv_bfloat16 h, l; split2(v, h, l);
        g_x_hi[row * DD + c] = h; g_x_lo[row * DD + c] = l;
        ss += v * v;
    }
    ss = blk_sum256(ss, sb);
    if (threadIdx.x == 0) g_rs[row] = rsqrtf(ss * (1.0f / DD) + EPSR);
}

__global__ __launch_bounds__(256) void k_init_ws(const float* __restrict__ wsrc)
{
    int i = blockIdx.x * 256 + threadIdx.x;
    g_ws[i] = wsrc[i & (SS * DD - 1)];
}

__global__ __launch_bounds__(256) void k_cw(const float* __restrict__ cw,
                                            const float* __restrict__ npw)
{
    int i = blockIdx.x * 256 + threadIdx.x;
    g_cw[i] = cw[i] * npw[i & (DD - 1)];
}

// warp-per-row compete logits; cw staged through smem in 256-col chunks
__global__ __launch_bounds__(256) void k_compete(const float* __restrict__ x,
                                                 const float* __restrict__ cb)
{
    __shared__ float scw[SS][256];
    int tid = threadIdx.x;
    int w = blockIdx.x * 8 + (tid >> 5);
    int lid = tid & 31;
    const float* xr = x + (size_t)w * DD;
    float acc[SS] = {};
    for (int kc = 0; kc < DD; kc += 256) {
        #pragma unroll
        for (int j = 0; j < 4; ++j) {
            int id = j * 256 + tid;             // float4 id, 1024 total
            int s = id >> 6; int q = (id & 63) * 4;
            *(float4*)(&scw[s][q]) = *(const float4*)(g_cw + (size_t)s * DD + kc + q);
        }
        __syncthreads();
        #pragma unroll
        for (int i = 0; i < 2; ++i) {
            float4 xv = *(const float4*)(xr + kc + i * 128 + lid * 4);
            #pragma unroll
            for (int s = 0; s < SS; ++s) {
                float4 cv = *(const float4*)(&scw[s][i * 128 + lid * 4]);
                acc[s] += xv.x * cv.x + xv.y * cv.y + xv.z * cv.z + xv.w * cv.w;
            }
        }
        __syncthreads();
    }
    #pragma unroll
    for (int s = 0; s < SS; ++s)
        #pragma unroll
        for (int o = 16; o > 0; o >>= 1) acc[s] += __shfl_xor_sync(0xffffffffu, acc[s], o);
    if (lid == 0) {
        int b = w >> 11, l = w & (LL - 1);
        float rs = g_rs[w];
        #pragma unroll
        for (int s = 0; s < SS; ++s)
            g_logits[(size_t)(b * SS + s) * LL + l] = acc[s] * rs + cb[s];
    }
}

__global__ __launch_bounds__(256) void k_topk_xm(const float* __restrict__ x)
{
    __shared__ float sv[LL];
    __shared__ float rv[256];
    __shared__ int   ri[256];
    __shared__ float topv[KTOP];
    __shared__ int   topi[KTOP];
    __shared__ float wgt[KTOP];
    int r = blockIdx.x;
    int b = r >> 4;
    int tid = threadIdx.x;
    for (int i = tid; i < LL; i += 256) sv[i] = g_logits[(size_t)r * LL + i];
    __syncthreads();
    for (int k = 0; k < KTOP; ++k) {
        float bv = -INFINITY; int bi = 0x7fffffff;
        for (int i = tid; i < LL; i += 256) {
            float v = sv[i];
            if (v > bv || (v == bv && i < bi)) { bv = v; bi = i; }
        }
        rv[tid] = bv; ri[tid] = bi;
        __syncthreads();
        for (int off = 128; off > 0; off >>= 1) {
            if (tid < off) {
                float v2 = rv[tid + off]; int i2 = ri[tid + off];
                if (v2 > rv[tid] || (v2 == rv[tid] && i2 < ri[tid])) { rv[tid] = v2; ri[tid] = i2; }
            }
            __syncthreads();
        }
        if (tid == 0) { topv[k] = rv[0]; topi[k] = ri[0]; sv[ri[0]] = -INFINITY; }
        __syncthreads();
    }
    if (tid == 0) {
        float m = topv[0];
        float e[KTOP]; float ssum = 0.f;
        #pragma unroll
        for (int k = 0; k < KTOP; ++k) { e[k] = expf(topv[k] - m); ssum += e[k]; }
        #pragma unroll
        for (int k = 0; k < KTOP; ++k) wgt[k] = e[k] / ssum;
    }
    __syncthreads();
    float w0 = wgt[0], w1 = wgt[1], w2 = wgt[2], w3 = wgt[3];
    const float* x0 = x + ((size_t)b * LL + topi[0]) * DD;
    const float* x1 = x + ((size_t)b * LL + topi[1]) * DD;
    const float* x2 = x + ((size_t)b * LL + topi[2]) * DD;
    const float* x3 = x + ((size_t)b * LL + topi[3]) * DD;
    float* xo = g_xm + (size_t)r * DD;
    for (int d = tid; d < DD; d += 256)
        xo[d] = w0 * x0[d] + w1 * x1[d] + w2 * x2[d] + w3 * x3[d];
}

// 64-row GEMM: out[r][n] = bias[n] + (res?res:0) + sum_k A[r][k]*W[n][k]
__global__ __launch_bounds__(256) void k_sg(const float* __restrict__ A,
                                            const float* __restrict__ W,
                                            const float* __restrict__ bias,
                                            const float* __restrict__ res,
                                            float* __restrict__ out, int Nout)
{
    const int n0 = blockIdx.x * 64;
    __shared__ float As[32][64];
    __shared__ float Ws[32][64];
    int tid = threadIdx.x;
    int tx = tid & 15, ty = tid >> 4;
    float acc[4][4] = {};
    for (int kc = 0; kc < DD; kc += 32) {
        #pragma unroll
        for (int it = 0; it < 2; ++it) {
            int idx = it * 256 + tid;
            int r = idx >> 3; int q = (idx & 7) * 4;
            float4 a = *(const float4*)(A + (size_t)r * DD + kc + q);
            As[q+0][r] = a.x; As[q+1][r] = a.y; As[q+2][r] = a.z; As[q+3][r] = a.w;
            float4 w = *(const float4*)(W + (size_t)(n0 + r) * DD + kc + q);
            Ws[q+0][r] = w.x; Ws[q+1][r] = w.y; Ws[q+2][r] = w.z; Ws[q+3][r] = w.w;
        }
        __syncthreads();
        #pragma unroll
        for (int k = 0; k < 32; ++k) {
            float a[4], b[4];
            #pragma unroll
            for (int i = 0; i < 4; ++i) a[i] = As[k][ty * 4 + i];
            #pragma unroll
            for (int j = 0; j < 4; ++j) b[j] = Ws[k][tx * 4 + j];
            #pragma unroll
            for (int i = 0; i < 4; ++i)
                #pragma unroll
                for (int j = 0; j < 4; ++j) acc[i][j] += a[i] * b[j];
        }
        __syncthreads();
    }
    #pragma unroll
    for (int i = 0; i < 4; ++i) {
        int r = ty * 4 + i;
        #pragma unroll
        for (int j = 0; j < 4; ++j) {
            int n = n0 + tx * 4 + j;
            float v = bias[n] + acc[i][j];
            if (res) v += res[(size_t)r * Nout + n];
            out[(size_t)r * Nout + n] = v;
        }
    }
}

// row rms. WHICH=0: g_t->g_ws. WHICH=1: g_y->xout + bf16 split + g_rs
template <int WHICH>
__global__ __launch_bounds__(256) void k_rmsn(float* __restrict__ xout,
                                              const float* __restrict__ w)
{
    __shared__ float sb[9];
    const float* in  = (WHICH == 0) ? g_t  : g_y;
    float*       out = (WHICH == 0) ? g_ws : xout;
    size_t row = blockIdx.x;
    const float* ir = in + row * DD;
    float v[8]; float ss = 0.f;
    #pragma unroll
    for (int i = 0; i < 8; ++i) { v[i] = ir[threadIdx.x + i * 256]; ss += v[i] * v[i]; }
    ss = blk_sum256(ss, sb);
    float rs = rsqrtf(ss * (1.0f / DD) + EPSR);
    float* orow = out + row * DD;
    float ss2 = 0.f;
    #pragma unroll
    for (int i = 0; i < 8; ++i) {
        int c = threadIdx.x + i * 256;
        float o = v[i] * rs * w[c];
        orow[c] = o;
        if (WHICH == 1) {
            __nv_bfloat16 h, l; split2(o, h, l);
            g_x_hi[row * DD + c] = h; g_x_lo[row * DD + c] = l;
        }
        ss2 += o * o;
    }
    if (WHICH == 1) {
        ss2 = blk_sum256(ss2, sb);
        if (threadIdx.x == 0) g_rs[row] = rsqrtf(ss2 * (1.0f / DD) + EPSR);
    }
}

__global__ __launch_bounds__(256) void k_c(const float* __restrict__ ipb)
{
    int o = blockIdx.x * 256 + threadIdx.x;
    int b = o / (HH * SS);
    int h = (o / SS) % HH;
    int s = o % SS;
    const float* kkrow = g_kv + ((size_t)(b * SS + s)) * (2 * DD);
    float acc = 0.f;
    #pragma unroll 8
    for (int j = 0; j < HDH; ++j) acc += ipb[h * HDH + j] * kkrow[h * HDH + j];
    g_c[(size_t)b * HS + h * SS + s] = acc;
}

// M[b, h*16+s, n] = sum_j kk[b,s,h*64+j] * wq[h*64+j][n]  -> bf16 hi/lo
__global__ __launch_bounds__(256) void k_m(const float* __restrict__ wq)
{
    int h = blockIdx.y; int n0 = blockIdx.x * 64;
    __shared__ float As[64][68];
    __shared__ float Bs[64][68];
    int tid = threadIdx.x;
    #pragma unroll
    for (int it = 0; it < 4; ++it) {
        int idx = it * 256 + tid;
        int r = idx >> 4; int q = (idx & 15) * 4;
        float4 a = *(const float4*)(g_kv + (size_t)r * (2 * DD) + h * HDH + q);
        *(float4*)(&As[r][q]) = a;
        float4 w = *(const float4*)(wq + (size_t)(h * HDH + r) * DD + n0 + q);
        *(float4*)(&Bs[r][q]) = w;
    }
    __syncthreads();
    int tx = tid & 15, ty = tid >> 4;
    float acc[4][4] = {};
    #pragma unroll 4
    for (int j = 0; j < 64; ++j) {
        float a[4], b[4];
        #pragma unroll
        for (int i = 0; i < 4; ++i) a[i] = As[ty * 4 + i][j];
        *(float4*)b = *(const float4*)(&Bs[j][tx * 4]);
        #pragma unroll
        for (int i = 0; i < 4; ++i)
            #pragma unroll
            for (int jj = 0; jj < 4; ++jj) acc[i][jj] += a[i] * b[jj];
    }
    #pragma unroll
    for (int i = 0; i < 4; ++i) {
        int r = ty * 4 + i; int b = r >> 4; int s = r & 15;
        size_t base = ((size_t)b * HS + h * SS + s) * DD + n0 + tx * 4;
        #pragma unroll
        for (int jj = 0; jj < 4; ++jj) {
            __nv_bfloat16 hh, ll; split2(acc[i][jj], hh, ll);
            g_m_hi[base + jj] = hh; g_m_lo[base + jj] = ll;
        }
    }
}

// P^T[b, n, h*16+s] = sum_j vv[b,s,h*64+j] * opw[n][h*64+j]  -> bf16 hi/lo
__global__ __launch_bounds__(256) void k_p(const float* __restrict__ Ow)
{
    int h = blockIdx.y; int n0 = blockIdx.x * 64;
    __shared__ float As[64][68];
    __shared__ float Bs[64][68];
    int tid = threadIdx.x;
    #pragma unroll
    for (int it = 0; it < 4; ++it) {
        int idx = it * 256 + tid;
        int r = idx >> 4; int q = (idx & 15) * 4;
        float4 a = *(const float4*)(g_kv + (size_t)r * (2 * DD) + DD + h * HDH + q);
        *(float4*)(&As[r][q]) = a;
        float4 w = *(const float4*)(Ow + (size_t)(n0 + r) * DD + h * HDH + q);
        Bs[q+0][r] = w.x; Bs[q+1][r] = w.y; Bs[q+2][r] = w.z; Bs[q+3][r] = w.w;
    }
    __syncthreads();
    int tx = tid & 15, ty = tid >> 4;
    float acc[4][4] = {};
    #pragma unroll 4
    for (int j = 0; j < 64; ++j) {
        float a[4], b[4];
        #pragma unroll
        for (int i = 0; i < 4; ++i) a[i] = As[ty * 4 + i][j];
        *(float4*)b = *(const float4*)(&Bs[j][tx * 4]);
        #pragma unroll
        for (int i = 0; i < 4; ++i)
            #pragma unroll
            for (int jj = 0; jj < 4; ++jj) acc[i][jj] += a[i] * b[jj];
    }
    #pragma unroll
    for (int i = 0; i < 4; ++i) {
        int r = ty * 4 + i; int b = r >> 4; int s = r & 15;
        #pragma unroll
        for (int jj = 0; jj < 4; ++jj) {
            int n = n0 + tx * 4 + jj;
            size_t a2 = ((size_t)b * DD + n) * HS + h * SS + s;
            __nv_bfloat16 hh, ll; split2(acc[i][jj], hh, ll);
            g_p_hi[a2] = hh; g_p_lo[a2] = ll;
        }
    }
}

// ---------------- HMMA bf16-split GEMM (mma.sync, sm_100 baseline) ----------------
// EPI=1: att = softmax16( (x @ M^T + c) * scale )   K=2048
// EPI=0: g_y = x + ob + att @ P^T                   K=512
// Tile 128x128x32, 8 warps (2m x 4n), 64x32 warp tiles, double-buffered cp.async.
template <int EPI>
__global__ __launch_bounds__(256) void k_mmh(const float* __restrict__ xres,
                                             const float* __restrict__ ob)
{
    constexpr int KT = EPI ? DD : HS;
    constexpr int BR = EPI ? HS : DD;
    extern __shared__ char sbuf[];     // 2 stages x 32KB: AH,AL,BH,BL each 8KB

    int tid = threadIdx.x;
    int wid = tid >> 5, lane = tid & 31;
    int wm = wid >> 2, wn = wid & 3;
    int g = lane >> 2, t = lane & 3;
    int b  = blockIdx.z;
    int m0 = blockIdx.x * 128;
    int n0 = blockIdx.y * 128;

    const __nv_bfloat16* Ah = EPI ? g_x_hi : g_att_hi;
    const __nv_bfloat16* Al = EPI ? g_x_lo : g_att_lo;
    const __nv_bfloat16* Bh = EPI ? g_m_hi : g_p_hi;
    const __nv_bfloat16* Bl = EPI ? g_m_lo : g_p_lo;
    const char* gAh = (const char*)(Ah + ((size_t)b * LL + m0) * KT);
    const char* gAl = (const char*)(Al + ((size_t)b * LL + m0) * KT);
    const char* gBh = (const char*)(Bh + ((size_t)b * BR + n0) * KT);
    const char* gBl = (const char*)(Bl + ((size_t)b * BR + n0) * KT);
    const int strideB = KT * 2;

    uint32_t s0 = smem_u32(sbuf);

    auto load_stage = [&](int st, int ktb) {
        uint32_t base = s0 + st * 32768;
        const char* gp[4] = { gAh, gAl, gBh, gBl };
        #pragma unroll
        for (int p = 0; p < 4; ++p) {
            #pragma unroll
            for (int i = 0; i < 2; ++i) {
                int ch = i * 256 + tid;          // 512 chunks of 16B per part
                int r = ch >> 2, c = ch & 3;
                const char* src = gp[p] + (size_t)r * strideB + ktb + c * 16;
                uint32_t dst = base + p * 8192 + r * 64 + ((c ^ ((r >> 1) & 3)) << 4);
                cpasync16(dst, src);
            }
        }
    };

    float acc[4][4][4] = {};

    const int nk = KT / 32;
    load_stage(0, 0);
    asm volatile("cp.async.commit_group;" ::: "memory");
    for (int i = 0; i < nk; ++i) {
        if (i + 1 < nk) {
            load_stage((i + 1) & 1, (i + 1) * 64);
            asm volatile("cp.async.commit_group;" ::: "memory");
            asm volatile("cp.async.wait_group 1;" ::: "memory");
        } else {
            asm volatile("cp.async.wait_group 0;" ::: "memory");
        }
        __syncthreads();
        uint32_t sA  = s0 + (i & 1) * 32768;
        uint32_t sAl = sA + 8192;
        uint32_t sBh = sA + 16384;
        uint32_t sBl = sA + 24576;
        #pragma unroll
        for (int ks = 0; ks < 2; ++ks) {
            int w0 = ks * 8 + t;
            uint32_t bh[4][2], bl[4][2];
            #pragma unroll
            for (int nf = 0; nf < 4; ++nf) {
                int rb = wn * 32 + nf * 8 + g;
                bh[nf][0] = lds32(sBh, rb, w0); bh[nf][1] = lds32(sBh, rb, w0 + 4);
                bl[nf][0] = lds32(sBl, rb, w0); bl[nf][1] = lds32(sBl, rb, w0 + 4);
            }
            #pragma unroll
            for (int mf = 0; mf < 4; ++mf) {
                int ra = wm * 64 + mf * 16 + g;
                uint32_t ah[4], al[4];
                ah[0] = lds32(sA, ra, w0);     ah[1] = lds32(sA, ra + 8, w0);
                ah[2] = lds32(sA, ra, w0 + 4); ah[3] = lds32(sA, ra + 8, w0 + 4);
                al[0] = lds32(sAl, ra, w0);     al[1] = lds32(sAl, ra + 8, w0);
                al[2] = lds32(sAl, ra, w0 + 4); al[3] = lds32(sAl, ra + 8, w0 + 4);
                #pragma unroll
                for (int nf = 0; nf < 4; ++nf) {
                    mma16816(acc[mf][nf], ah, bh[nf]);
                    mma16816(acc[mf][nf], ah, bl[nf]);
                    mma16816(acc[mf][nf], al, bh[nf]);
                }
            }
        }
        __syncthreads();
    }

    if (EPI == 0) {
        #pragma unroll
        for (int mf = 0; mf < 4; ++mf) {
            #pragma unroll
            for (int rs = 0; rs < 2; ++rs) {
                size_t row = (size_t)b * LL + m0 + wm * 64 + mf * 16 + g + rs * 8;
                #pragma unroll
                for (int nf = 0; nf < 4; ++nf) {
                    int col = n0 + wn * 32 + nf * 8 + 2 * t;
                    float2 xr = *(const float2*)(xres + row * DD + col);
                    float2 o;
                    o.x = xr.x + ob[col]     + acc[mf][nf][rs * 2 + 0];
                    o.y = xr.y + ob[col + 1] + acc[mf][nf][rs * 2 + 1];
                    *(float2*)(g_y + row * DD + col) = o;
                }
            }
        }
    } else {
        float cbv[8];
        #pragma unroll
        for (int nf = 0; nf < 4; ++nf) {
            int col = n0 + wn * 32 + nf * 8 + 2 * t;
            cbv[nf * 2 + 0] = g_c[(size_t)b * HS + col];
            cbv[nf * 2 + 1] = g_c[(size_t)b * HS + col + 1];
        }
        #pragma unroll
        for (int mf = 0; mf < 4; ++mf) {
            #pragma unroll
            for (int rs = 0; rs < 2; ++rs) {
                size_t row = (size_t)b * LL + m0 + wm * 64 + mf * 16 + g + rs * 8;
                float v[8];
                #pragma unroll
                for (int nf = 0; nf < 4; ++nf) {
                    v[nf * 2 + 0] = (acc[mf][nf][rs * 2 + 0] + cbv[nf * 2 + 0]) * ATT_SCALE;
                    v[nf * 2 + 1] = (acc[mf][nf][rs * 2 + 1] + cbv[nf * 2 + 1]) * ATT_SCALE;
                }
                #pragma unroll
                for (int g2 = 0; g2 < 2; ++g2) {
                    float* vv = v + g2 * 4;
                    float mx = fmaxf(fmaxf(vv[0], vv[1]), fmaxf(vv[2], vv[3]));
                    mx = fmaxf(mx, __shfl_xor_sync(0xffffffffu, mx, 1));
                    mx = fmaxf(mx, __shfl_xor_sync(0xffffffffu, mx, 2));
                    float e[4]; float sm = 0.f;
                    #pragma unroll
                    for (int j = 0; j < 4; ++j) { e[j] = __expf(vv[j] - mx); sm += e[j]; }
                    sm += __shfl_xor_sync(0xffffffffu, sm, 1);
                    sm += __shfl_xor_sync(0xffffffffu, sm, 2);
                    float inv = 1.0f / sm;
                    #pragma unroll
                    for (int nfo = 0; nfo < 2; ++nfo) {
                        int col = n0 + wn * 32 + g2 * 16 + nfo * 8 + 2 * t;
                        float p0 = e[nfo * 2 + 0] * inv;
                        float p1 = e[nfo * 2 + 1] * inv;
                        __nv_bfloat16 h0, l0, h1, l1;
                        split2(p0, h0, l0); split2(p1, h1, l1);
                        __nv_bfloat162 hv; hv.x = h0; hv.y = h1;
                        __nv_bfloat162 lv; lv.x = l0; lv.y = l1;
                        *(__nv_bfloat162*)(&g_att_hi[row * HS + col]) = hv;
                        *(__nv_bfloat162*)(&g_att_lo[row * HS + col]) = lv;
                    }
                }
            }
        }
    }
}

// ---------------- launch ----------------
extern "C" void kernel_launch(void* const* d_in, const int* in_sizes, int n_in,
                              void* d_out, int out_size)
{
    const float* x_in = (const float*)d_in[0];
    const float* ws_in= (const float*)d_in[1];
    const float* cw   = (const float*)d_in[2];
    const float* cb   = (const float*)d_in[3];
    const float* ww   = (const float*)d_in[4];
    const float* wb   = (const float*)d_in[5];
    const float* ipw  = (const float*)d_in[6];
    const float* ipb  = (const float*)d_in[7];
    const float* opw  = (const float*)d_in[8];
    const float* opb  = (const float*)d_in[9];
    const float* npw  = (const float*)d_in[12];
    const float* npow = (const float*)d_in[13];
    float* xbuf = (float*)d_out;

    float *p_ws, *p_xm, *p_t, *p_kv;
    cudaGetSymbolAddress((void**)&p_ws, g_ws);
    cudaGetSymbolAddress((void**)&p_xm, g_xm);
    cudaGetSymbolAddress((void**)&p_t,  g_t);
    cudaGetSymbolAddress((void**)&p_kv, g_kv);

    const int SMEM_MM = 65536;
    cudaFuncSetAttribute((const void*)k_mmh<0>, cudaFuncAttributeMaxDynamicSharedMemorySize, SMEM_MM);
    cudaFuncSetAttribute((const void*)k_mmh<1>, cudaFuncAttributeMaxDynamicSharedMemorySize, SMEM_MM);

    k_init_x<<<BB*LL, 256>>>(x_in, xbuf);
    k_init_ws<<<BB*SS*DD/256, 256>>>(ws_in);
    k_cw<<<SS*DD/256, 256>>>(cw, npw);

    for (int blk = 0; blk < 2; ++blk) {
        k_compete<<<BB*LL/8, 256>>>(xbuf, cb);
        k_topk_xm<<<BB*SS, 256>>>(xbuf);
        k_sg<<<DD/64, 256>>>(p_xm, ww, wb, p_ws, p_t, DD);
        k_rmsn<0><<<BB*SS, 256>>>(xbuf, npow);
        k_sg<<<2*DD/64, 256>>>(p_ws, ipw + (size_t)DD*DD, ipb + DD, nullptr, p_kv, 2*DD);
        k_c<<<BB*HH*SS/256, 256>>>(ipb);
        k_m<<<dim3(DD/64, HH), 256>>>(ipw);
        k_p<<<dim3(DD/64, HH), 256>>>(opw);
        k_mmh<1><<<dim3(LL/128, HS/128, BB), 256, SMEM_MM>>>(nullptr, nullptr);
        k_mmh<0><<<dim3(LL/128, DD/128, BB), 256, SMEM_MM>>>(xbuf, opb);
        k_rmsn<1><<<BB*LL, 256>>>(xbuf, npow);
    }
}

// round 7
// speedup vs baseline: 2.3522x; 1.2631x over previous
#include <cuda_runtime.h>
#include <cuda_bf16.h>
#include <math.h>
#include <stdint.h>

#define BB   4
#define LL   2048
#define DD   2048
#define SS   16
#define KTOP 4
#define HH   32
#define HDH  64
#define HS   512
#define EPSR 1e-6f
#define ATT_SCALE 0.125f

// fp32 scratch
__device__ __align__(128) float g_ws    [BB*SS*DD];
__device__ __align__(128) float g_cw    [SS*DD];
__device__ __align__(128) float g_logits[BB*SS*LL];
__device__ __align__(128) float g_xm    [BB*SS*DD];
__device__ __align__(128) float g_t     [BB*SS*DD];
__device__ __align__(128) float g_kv    [BB*SS*2*DD];
__device__ __align__(128) float g_c     [BB*HS];
__device__ __align__(128) float g_y     [(size_t)BB*LL*DD];
__device__ __align__(128) float g_rs    [BB*LL];
__device__ __align__(128) float g_part  [4][64*2*DD];
// bf16 split operands for tensor-core GEMMs
__device__ __align__(128) __nv_bfloat16 g_x_hi [(size_t)BB*LL*DD];
__device__ __align__(128) __nv_bfloat16 g_x_lo [(size_t)BB*LL*DD];
__device__ __align__(128) __nv_bfloat16 g_m_hi [(size_t)BB*HS*DD];
__device__ __align__(128) __nv_bfloat16 g_m_lo [(size_t)BB*HS*DD];
__device__ __align__(128) __nv_bfloat16 g_p_hi [(size_t)BB*DD*HS];   // [b][d][hs]
__device__ __align__(128) __nv_bfloat16 g_p_lo [(size_t)BB*DD*HS];
__device__ __align__(128) __nv_bfloat16 g_att_hi[(size_t)BB*LL*HS];
__device__ __align__(128) __nv_bfloat16 g_att_lo[(size_t)BB*LL*HS];

// ---------------- helpers ----------------
__device__ __forceinline__ uint32_t smem_u32(const void* p) {
    uint32_t a;
    asm("{ .reg .u64 t; cvta.to.shared.u64 t, %1; cvt.u32.u64 %0, t; }" : "=r"(a) : "l"(p));
    return a;
}
__device__ __forceinline__ void split2(float v, __nv_bfloat16& h, __nv_bfloat16& l) {
    h = __float2bfloat16_rn(v);
    l = __float2bfloat16_rn(v - __bfloat162float(h));
}
__device__ __forceinline__ float blk_sum256(float v, float* sb)
{
    #pragma unroll
    for (int o = 16; o > 0; o >>= 1) v += __shfl_down_sync(0xffffffffu, v, o);
    if ((threadIdx.x & 31) == 0) sb[threadIdx.x >> 5] = v;
    __syncthreads();
    if (threadIdx.x == 0) {
        float t = 0.f;
        #pragma unroll
        for (int i = 0; i < 8; ++i) t += sb[i];
        sb[8] = t;
    }
    __syncthreads();
    float r = sb[8];
    __syncthreads();
    return r;
}
__device__ __forceinline__ void mma16816(float* c, const uint32_t* a, const uint32_t* b) {
    asm volatile("mma.sync.aligned.m16n8k16.row.col.f32.bf16.bf16.f32 "
        "{%0,%1,%2,%3},{%4,%5,%6,%7},{%8,%9},{%0,%1,%2,%3};"
        : "+f"(c[0]), "+f"(c[1]), "+f"(c[2]), "+f"(c[3])
        : "r"(a[0]), "r"(a[1]), "r"(a[2]), "r"(a[3]), "r"(b[0]), "r"(b[1]));
}
__device__ __forceinline__ void ldm_x4(uint32_t* r, uint32_t a) {
    asm volatile("ldmatrix.sync.aligned.m8n8.x4.shared.b16 {%0,%1,%2,%3}, [%4];"
                 : "=r"(r[0]), "=r"(r[1]), "=r"(r[2]), "=r"(r[3]) : "r"(a));
}
__device__ __forceinline__ void cpasync16(uint32_t dst, const void* src) {
    asm volatile("cp.async.cg.shared.global [%0], [%1], 16;" :: "r"(dst), "l"(src) : "memory");
}

// ---------------- small kernels ----------------
__global__ __launch_bounds__(256) void k_init_x(const float* __restrict__ xin,
                                                float* __restrict__ xout)
{
    __shared__ float sb[9];
    size_t row = blockIdx.x;
    const float* ir = xin + row * DD;
    float* orow = xout + row * DD;
    float ss = 0.f;
    #pragma unroll
    for (int i = 0; i < 8; ++i) {
        int c = threadIdx.x + i * 256;
        float v = ir[c];
        orow[c] = v;
        __nv_bfloat16 h, l; split2(v, h, l);
        g_x_hi[row * DD + c] = h; g_x_lo[row * DD + c] = l;
        ss += v * v;
    }
    ss = blk_sum256(ss, sb);
    if (threadIdx.x == 0) g_rs[row] = rsqrtf(ss * (1.0f / DD) + EPSR);
}

__global__ __launch_bounds__(256) void k_init_ws(const float* __restrict__ wsrc)
{
    int i = blockIdx.x * 256 + threadIdx.x;
    g_ws[i] = wsrc[i & (SS * DD - 1)];
}

__global__ __launch_bounds__(256) void k_cw(const float* __restrict__ cw,
                                            const float* __restrict__ npw)
{
    int i = blockIdx.x * 256 + threadIdx.x;
    g_cw[i] = cw[i] * npw[i & (DD - 1)];
}

// compete logits, 2 rows per warp, cw staged through smem
__global__ __launch_bounds__(256) void k_compete(const float* __restrict__ x,
                                                 const float* __restrict__ cb)
{
    __shared__ float scw[SS][256];
    int tid = threadIdx.x;
    int warp = tid >> 5, lid = tid & 31;
    int w0 = blockIdx.x * 16 + warp * 2;
    const float* xr0 = x + (size_t)w0 * DD;
    const float* xr1 = xr0 + DD;
    float acc[2][SS] = {};
    for (int kc = 0; kc < DD; kc += 256) {
        #pragma unroll
        for (int j = 0; j < 4; ++j) {
            int id = j * 256 + tid;
            int s = id >> 6; int q = (id & 63) * 4;
            *(float4*)(&scw[s][q]) = *(const float4*)(g_cw + (size_t)s * DD + kc + q);
        }
        __syncthreads();
        #pragma unroll
        for (int i = 0; i < 2; ++i) {
            float4 a0 = *(const float4*)(xr0 + kc + i * 128 + lid * 4);
            float4 a1 = *(const float4*)(xr1 + kc + i * 128 + lid * 4);
            #pragma unroll
            for (int s = 0; s < SS; ++s) {
                float4 cv = *(const float4*)(&scw[s][i * 128 + lid * 4]);
                acc[0][s] += a0.x * cv.x + a0.y * cv.y + a0.z * cv.z + a0.w * cv.w;
                acc[1][s] += a1.x * cv.x + a1.y * cv.y + a1.z * cv.z + a1.w * cv.w;
            }
        }
        __syncthreads();
    }
    #pragma unroll
    for (int r = 0; r < 2; ++r) {
        #pragma unroll
        for (int s = 0; s < SS; ++s)
            #pragma unroll
            for (int o = 16; o > 0; o >>= 1)
                acc[r][s] += __shfl_xor_sync(0xffffffffu, acc[r][s], o);
        if (lid == 0) {
            int w = w0 + r;
            int b = w >> 11, l = w & (LL - 1);
            float rs = g_rs[w];
            #pragma unroll
            for (int s = 0; s < SS; ++s)
                g_logits[(size_t)(b * SS + s) * LL + l] = acc[r][s] * rs + cb[s];
        }
    }
}

__global__ __launch_bounds__(256) void k_topk_xm(const float* __restrict__ x)
{
    __shared__ float sv[LL];
    __shared__ float rv[256];
    __shared__ int   ri[256];
    __shared__ float topv[KTOP];
    __shared__ int   topi[KTOP];
    __shared__ float wgt[KTOP];
    int r = blockIdx.x;
    int b = r >> 4;
    int tid = threadIdx.x;
    for (int i = tid; i < LL; i += 256) sv[i] = g_logits[(size_t)r * LL + i];
    __syncthreads();
    for (int k = 0; k < KTOP; ++k) {
        float bv = -INFINITY; int bi = 0x7fffffff;
        for (int i = tid; i < LL; i += 256) {
            float v = sv[i];
            if (v > bv || (v == bv && i < bi)) { bv = v; bi = i; }
        }
        rv[tid] = bv; ri[tid] = bi;
        __syncthreads();
        for (int off = 128; off > 0; off >>= 1) {
            if (tid < off) {
                float v2 = rv[tid + off]; int i2 = ri[tid + off];
                if (v2 > rv[tid] || (v2 == rv[tid] && i2 < ri[tid])) { rv[tid] = v2; ri[tid] = i2; }
            }
            __syncthreads();
        }
        if (tid == 0) { topv[k] = rv[0]; topi[k] = ri[0]; sv[ri[0]] = -INFINITY; }
        __syncthreads();
    }
    if (tid == 0) {
        float m = topv[0];
        float e[KTOP]; float ssum = 0.f;
        #pragma unroll
        for (int k = 0; k < KTOP; ++k) { e[k] = expf(topv[k] - m); ssum += e[k]; }
        #pragma unroll
        for (int k = 0; k < KTOP; ++k) wgt[k] = e[k] / ssum;
    }
    __syncthreads();
    float w0 = wgt[0], w1 = wgt[1], w2 = wgt[2], w3 = wgt[3];
    const float* x0 = x + ((size_t)b * LL + topi[0]) * DD;
    const float* x1 = x + ((size_t)b * LL + topi[1]) * DD;
    const float* x2 = x + ((size_t)b * LL + topi[2]) * DD;
    const float* x3 = x + ((size_t)b * LL + topi[3]) * DD;
    float* xo = g_xm + (size_t)r * DD;
    for (int d = tid; d < DD; d += 256)
        xo[d] = w0 * x0[d] + w1 * x1[d] + w2 * x2[d] + w3 * x3[d];
}

// split-K partial GEMM: part[kz][r][n] = sum_{k in slice} A[r][k]*W[n][k]; 64 rows
__global__ __launch_bounds__(256) void k_sgp(const float* __restrict__ A,
                                             const float* __restrict__ W,
                                             int Nout)
{
    const int n0 = blockIdx.x * 64;
    const int kz = blockIdx.y;
    __shared__ float As[32][64];
    __shared__ float Ws[32][64];
    int tid = threadIdx.x;
    int tx = tid & 15, ty = tid >> 4;
    float acc[4][4] = {};
    for (int kc = kz * 512; kc < kz * 512 + 512; kc += 32) {
        #pragma unroll
        for (int it = 0; it < 2; ++it) {
            int idx = it * 256 + tid;
            int r = idx >> 3; int q = (idx & 7) * 4;
            float4 a = *(const float4*)(A + (size_t)r * DD + kc + q);
            As[q+0][r] = a.x; As[q+1][r] = a.y; As[q+2][r] = a.z; As[q+3][r] = a.w;
            float4 w = *(const float4*)(W + (size_t)(n0 + r) * DD + kc + q);
            Ws[q+0][r] = w.x; Ws[q+1][r] = w.y; Ws[q+2][r] = w.z; Ws[q+3][r] = w.w;
        }
        __syncthreads();
        #pragma unroll
        for (int k = 0; k < 32; ++k) {
            float a[4], b[4];
            #pragma unroll
            for (int i = 0; i < 4; ++i) a[i] = As[k][ty * 4 + i];
            #pragma unroll
            for (int j = 0; j < 4; ++j) b[j] = Ws[k][tx * 4 + j];
            #pragma unroll
            for (int i = 0; i < 4; ++i)
                #pragma unroll
                for (int j = 0; j < 4; ++j) acc[i][j] += a[i] * b[j];
        }
        __syncthreads();
    }
    #pragma unroll
    for (int i = 0; i < 4; ++i) {
        int r = ty * 4 + i;
        #pragma unroll
        for (int j = 0; j < 4; ++j)
            g_part[kz][(size_t)r * Nout + n0 + tx * 4 + j] = acc[i][j];
    }
}

__global__ __launch_bounds__(256) void k_sgr(const float* __restrict__ bias,
                                             const float* __restrict__ res,
                                             float* __restrict__ out, int Nout)
{
    int i = blockIdx.x * 256 + threadIdx.x;       // < 64*Nout
    int n = i % Nout;
    float v = bias[n] + g_part[0][i] + g_part[1][i] + g_part[2][i] + g_part[3][i];
    if (res) v += res[i];
    out[i] = v;
}

// row rms. WHICH=0: g_t->g_ws. WHICH=1: g_y->xout + bf16 split + g_rs
template <int WHICH>
__global__ __launch_bounds__(256) void k_rmsn(float* __restrict__ xout,
                                              const float* __restrict__ w)
{
    __shared__ float sb[9];
    const float* in  = (WHICH == 0) ? g_t  : g_y;
    float*       out = (WHICH == 0) ? g_ws : xout;
    size_t row = blockIdx.x;
    const float* ir = in + row * DD;
    float v[8]; float ss = 0.f;
    #pragma unroll
    for (int i = 0; i < 8; ++i) { v[i] = ir[threadIdx.x + i * 256]; ss += v[i] * v[i]; }
    ss = blk_sum256(ss, sb);
    float rs = rsqrtf(ss * (1.0f / DD) + EPSR);
    float* orow = out + row * DD;
    float ss2 = 0.f;
    #pragma unroll
    for (int i = 0; i < 8; ++i) {
        int c = threadIdx.x + i * 256;
        float o = v[i] * rs * w[c];
        orow[c] = o;
        if (WHICH == 1) {
            __nv_bfloat16 h, l; split2(o, h, l);
            g_x_hi[row * DD + c] = h; g_x_lo[row * DD + c] = l;
        }
        ss2 += o * o;
    }
    if (WHICH == 1) {
        ss2 = blk_sum256(ss2, sb);
        if (threadIdx.x == 0) g_rs[row] = rsqrtf(ss2 * (1.0f / DD) + EPSR);
    }
}

__global__ __launch_bounds__(256) void k_c(const float* __restrict__ ipb)
{
    int o = blockIdx.x * 256 + threadIdx.x;
    int b = o / (HH * SS);
    int h = (o / SS) % HH;
    int s = o % SS;
    const float* kkrow = g_kv + ((size_t)(b * SS + s)) * (2 * DD);
    float acc = 0.f;
    #pragma unroll 8
    for (int j = 0; j < HDH; ++j) acc += ipb[h * HDH + j] * kkrow[h * HDH + j];
    g_c[(size_t)b * HS + h * SS + s] = acc;
}

// M[b, h*16+s, n] = sum_j kk[b,s,h*64+j] * wq[h*64+j][n]  -> bf16 hi/lo
__global__ __launch_bounds__(256) void k_m(const float* __restrict__ wq)
{
    int h = blockIdx.y; int n0 = blockIdx.x * 64;
    __shared__ float As[64][68];
    __shared__ float Bs[64][68];
    int tid = threadIdx.x;
    #pragma unroll
    for (int it = 0; it < 4; ++it) {
        int idx = it * 256 + tid;
        int r = idx >> 4; int q = (idx & 15) * 4;
        float4 a = *(const float4*)(g_kv + (size_t)r * (2 * DD) + h * HDH + q);
        *(float4*)(&As[r][q]) = a;
        float4 w = *(const float4*)(wq + (size_t)(h * HDH + r) * DD + n0 + q);
        *(float4*)(&Bs[r][q]) = w;
    }
    __syncthreads();
    int tx = tid & 15, ty = tid >> 4;
    float acc[4][4] = {};
    #pragma unroll 4
    for (int j = 0; j < 64; ++j) {
        float a[4], b[4];
        #pragma unroll
        for (int i = 0; i < 4; ++i) a[i] = As[ty * 4 + i][j];
        *(float4*)b = *(const float4*)(&Bs[j][tx * 4]);
        #pragma unroll
        for (int i = 0; i < 4; ++i)
            #pragma unroll
            for (int jj = 0; jj < 4; ++jj) acc[i][jj] += a[i] * b[jj];
    }
    #pragma unroll
    for (int i = 0; i < 4; ++i) {
        int r = ty * 4 + i; int b = r >> 4; int s = r & 15;
        size_t base = ((size_t)b * HS + h * SS + s) * DD + n0 + tx * 4;
        #pragma unroll
        for (int jj = 0; jj < 4; ++jj) {
            __nv_bfloat16 hh, ll; split2(acc[i][jj], hh, ll);
            g_m_hi[base + jj] = hh; g_m_lo[base + jj] = ll;
        }
    }
}

// P^T[b, n, h*16+s] = sum_j vv[b,s,h*64+j] * opw[n][h*64+j]  -> bf16 hi/lo
__global__ __launch_bounds__(256) void k_p(const float* __restrict__ Ow)
{
    int h = blockIdx.y; int n0 = blockIdx.x * 64;
    __shared__ float As[64][68];
    __shared__ float Bs[64][68];
    int tid = threadIdx.x;
    #pragma unroll
    for (int it = 0; it < 4; ++it) {
        int idx = it * 256 + tid;
        int r = idx >> 4; int q = (idx & 15) * 4;
        float4 a = *(const float4*)(g_kv + (size_t)r * (2 * DD) + DD + h * HDH + q);
        *(float4*)(&As[r][q]) = a;
        float4 w = *(const float4*)(Ow + (size_t)(n0 + r) * DD + h * HDH + q);
        Bs[q+0][r] = w.x; Bs[q+1][r] = w.y; Bs[q+2][r] = w.z; Bs[q+3][r] = w.w;
    }
    __syncthreads();
    int tx = tid & 15, ty = tid >> 4;
    float acc[4][4] = {};
    #pragma unroll 4
    for (int j = 0; j < 64; ++j) {
        float a[4], b[4];
        #pragma unroll
        for (int i = 0; i < 4; ++i) a[i] = As[ty * 4 + i][j];
        *(float4*)b = *(const float4*)(&Bs[j][tx * 4]);
        #pragma unroll
        for (int i = 0; i < 4; ++i)
            #pragma unroll
            for (int jj = 0; jj < 4; ++jj) acc[i][jj] += a[i] * b[jj];
    }
    #pragma unroll
    for (int i = 0; i < 4; ++i) {
        int r = ty * 4 + i; int b = r >> 4; int s = r & 15;
        #pragma unroll
        for (int jj = 0; jj < 4; ++jj) {
            int n = n0 + tx * 4 + jj;
            size_t a2 = ((size_t)b * DD + n) * HS + h * SS + s;
            __nv_bfloat16 hh, ll; split2(acc[i][jj], hh, ll);
            g_p_hi[a2] = hh; g_p_lo[a2] = ll;
        }
    }
}

// ---------------- HMMA bf16-split GEMM with ldmatrix ----------------
// EPI=1: att = softmax16( (x @ M^T + c) * scale )   K=2048, tile 128x64
// EPI=0: g_y = x + ob + att @ P^T                   K=512,  tile 128x128
template <int EPI>
__global__ __launch_bounds__(256) void k_mmh(const float* __restrict__ xres,
                                             const float* __restrict__ ob)
{
    constexpr int KT = EPI ? DD : HS;
    constexpr int BR = EPI ? HS : DD;
    constexpr int NT = EPI ? 64 : 128;
    constexpr int WN = EPI ? 2 : 4;
    constexpr int WM = 8 / WN;
    constexpr int MF = 128 / (WM * 16);
    constexpr int NF = 4;
    constexpr int WMT = MF * 16;              // warp m-tile
    constexpr int B_OFF  = 16384;
    constexpr int BL_OFF = 16384 + NT * 64;
    constexpr int STG = 16384 + NT * 128;     // bytes per stage
    extern __shared__ char sbuf[];

    int tid = threadIdx.x;
    int wid = tid >> 5, lane = tid & 31;
    int wm = EPI ? (wid >> 1) : (wid >> 2);
    int wn = EPI ? (wid & 1)  : (wid & 3);
    int g = lane >> 2, t = lane & 3;
    int b  = blockIdx.z;
    int m0 = blockIdx.x * 128;
    int n0 = blockIdx.y * NT;

    int sel = lane >> 3, l7 = lane & 7;
    int a_row_rel = l7 + ((sel & 1) << 3);
    int a_csel    = sel >> 1;
    int b_row_rel = l7 + ((sel >> 1) << 3);
    int b_csel    = sel & 1;

    const __nv_bfloat16* Ah = EPI ? g_x_hi : g_att_hi;
    const __nv_bfloat16* Al = EPI ? g_x_lo : g_att_lo;
    const __nv_bfloat16* Bh = EPI ? g_m_hi : g_p_hi;
    const __nv_bfloat16* Bl = EPI ? g_m_lo : g_p_lo;
    const char* gAh = (const char*)(Ah + ((size_t)b * LL + m0) * KT);
    const char* gAl = (const char*)(Al + ((size_t)b * LL + m0) * KT);
    const char* gBh = (const char*)(Bh + ((size_t)b * BR + n0) * KT);
    const char* gBl = (const char*)(Bl + ((size_t)b * BR + n0) * KT);
    const int strideB = KT * 2;

    uint32_t s0 = smem_u32(sbuf);

    auto load_stage = [&](int st, int ktbytes) {
        uint32_t base = s0 + st * STG;
        #pragma unroll
        for (int p = 0; p < 2; ++p) {
            const char* gp = p ? gAl : gAh;
            #pragma unroll
            for (int i = 0; i < 2; ++i) {
                int ch = i * 256 + tid;
                int r = ch >> 2, c = ch & 3;
                cpasync16(base + p * 8192 + r * 64 + ((c ^ ((r >> 1) & 3)) << 4),
                          gp + (size_t)r * strideB + ktbytes + c * 16);
            }
        }
        #pragma unroll
        for (int p = 0; p < 2; ++p) {
            const char* gp = p ? gBl : gBh;
            uint32_t bb = base + (p ? BL_OFF : B_OFF);
            #pragma unroll
            for (int i = 0; i < NT * 4 / 256; ++i) {
                int ch = i * 256 + tid;
                int r = ch >> 2, c = ch & 3;
                cpasync16(bb + r * 64 + ((c ^ ((r >> 1) & 3)) << 4),
                          gp + (size_t)r * strideB + ktbytes + c * 16);
            }
        }
    };

    float acc[MF][NF][4] = {};

    const int nk = KT / 32;
    load_stage(0, 0);
    asm volatile("cp.async.commit_group;" ::: "memory");
    for (int i = 0; i < nk; ++i) {
        if (i + 1 < nk) {
            load_stage((i + 1) & 1, (i + 1) * 64);
            asm volatile("cp.async.commit_group;" ::: "memory");
            asm volatile("cp.async.wait_group 1;" ::: "memory");
        } else {
            asm volatile("cp.async.wait_group 0;" ::: "memory");
        }
        __syncthreads();
        uint32_t sA  = s0 + (i & 1) * STG;
        uint32_t sAl = sA + 8192;
        uint32_t sB  = sA + B_OFF;
        uint32_t sBl = sA + BL_OFF;
        #pragma unroll
        for (int ks = 0; ks < 2; ++ks) {
            uint32_t bh[NF][2], bl[NF][2];
            #pragma unroll
            for (int nfp = 0; nfp < NF / 2; ++nfp) {
                int row = wn * 32 + nfp * 16 + b_row_rel;
                uint32_t off = (uint32_t)row * 64 + (((2 * ks + b_csel) ^ ((row >> 1) & 3)) << 4);
                uint32_t r4[4];
                ldm_x4(r4, sB + off);
                bh[nfp*2][0]=r4[0]; bh[nfp*2][1]=r4[1]; bh[nfp*2+1][0]=r4[2]; bh[nfp*2+1][1]=r4[3];
                ldm_x4(r4, sBl + off);
                bl[nfp*2][0]=r4[0]; bl[nfp*2][1]=r4[1]; bl[nfp*2+1][0]=r4[2]; bl[nfp*2+1][1]=r4[3];
            }
            #pragma unroll
            for (int mf = 0; mf < MF; ++mf) {
                int row = wm * WMT + mf * 16 + a_row_rel;
                uint32_t off = (uint32_t)row * 64 + (((2 * ks + a_csel) ^ ((row >> 1) & 3)) << 4);
                uint32_t ah[4], al[4];
                ldm_x4(ah, sA + off);
                ldm_x4(al, sAl + off);
                #pragma unroll
                for (int nf = 0; nf < NF; ++nf) {
                    mma16816(acc[mf][nf], ah, bh[nf]);
                    mma16816(acc[mf][nf], ah, bl[nf]);
                    mma16816(acc[mf][nf], al, bh[nf]);
                }
            }
        }
        __syncthreads();
    }

    if (EPI == 0) {
        #pragma unroll
        for (int mf = 0; mf < MF; ++mf) {
            #pragma unroll
            for (int rs = 0; rs < 2; ++rs) {
                size_t row = (size_t)b * LL + m0 + wm * WMT + mf * 16 + g + rs * 8;
                #pragma unroll
                for (int nf = 0; nf < NF; ++nf) {
                    int col = n0 + wn * 32 + nf * 8 + 2 * t;
                    float2 xr = *(const float2*)(xres + row * DD + col);
                    float2 o;
                    o.x = xr.x + ob[col]     + acc[mf][nf][rs * 2 + 0];
                    o.y = xr.y + ob[col + 1] + acc[mf][nf][rs * 2 + 1];
                    *(float2*)(g_y + row * DD + col) = o;
                }
            }
        }
    } else {
        float cbv[8];
        #pragma unroll
        for (int nf = 0; nf < NF; ++nf) {
            int col = n0 + wn * 32 + nf * 8 + 2 * t;
            cbv[nf * 2 + 0] = g_c[(size_t)b * HS + col];
            cbv[nf * 2 + 1] = g_c[(size_t)b * HS + col + 1];
        }
        #pragma unroll
        for (int mf = 0; mf < MF; ++mf) {
            #pragma unroll
            for (int rs = 0; rs < 2; ++rs) {
                size_t row = (size_t)b * LL + m0 + wm * WMT + mf * 16 + g + rs * 8;
                float v[8];
                #pragma unroll
                for (int nf = 0; nf < NF; ++nf) {
                    v[nf * 2 + 0] = (acc[mf][nf][rs * 2 + 0] + cbv[nf * 2 + 0]) * ATT_SCALE;
                    v[nf * 2 + 1] = (acc[mf][nf][rs * 2 + 1] + cbv[nf * 2 + 1]) * ATT_SCALE;
                }
                #pragma unroll
                for (int g2 = 0; g2 < 2; ++g2) {
                    float* vv = v + g2 * 4;
                    float mx = fmaxf(fmaxf(vv[0], vv[1]), fmaxf(vv[2], vv[3]));
                    mx = fmaxf(mx, __shfl_xor_sync(0xffffffffu, mx, 1));
                    mx = fmaxf(mx, __shfl_xor_sync(0xffffffffu, mx, 2));
                    float e[4]; float sm = 0.f;
                    #pragma unroll
                    for (int j = 0; j < 4; ++j) { e[j] = __expf(vv[j] - mx); sm += e[j]; }
                    sm += __shfl_xor_sync(0xffffffffu, sm, 1);
                    sm += __shfl_xor_sync(0xffffffffu, sm, 2);
                    float inv = 1.0f / sm;
                    #pragma unroll
                    for (int nfo = 0; nfo < 2; ++nfo) {
                        int col = n0 + wn * 32 + g2 * 16 + nfo * 8 + 2 * t;
                        float p0 = e[nfo * 2 + 0] * inv;
                        float p1 = e[nfo * 2 + 1] * inv;
                        __nv_bfloat16 h0, l0, h1, l1;
                        split2(p0, h0, l0); split2(p1, h1, l1);
                        __nv_bfloat162 hv; hv.x = h0; hv.y = h1;
                        __nv_bfloat162 lv; lv.x = l0; lv.y = l1;
                        *(__nv_bfloat162*)(&g_att_hi[row * HS + col]) = hv;
                        *(__nv_bfloat162*)(&g_att_lo[row * HS + col]) = lv;
                    }
                }
            }
        }
    }
}

// ---------------- launch ----------------
extern "C" void kernel_launch(void* const* d_in, const int* in_sizes, int n_in,
                              void* d_out, int out_size)
{
    const float* x_in = (const float*)d_in[0];
    const float* ws_in= (const float*)d_in[1];
    const float* cw   = (const float*)d_in[2];
    const float* cb   = (const float*)d_in[3];
    const float* ww   = (const float*)d_in[4];
    const float* wb   = (const float*)d_in[5];
    const float* ipw  = (const float*)d_in[6];
    const float* ipb  = (const float*)d_in[7];
    const float* opw  = (const float*)d_in[8];
    const float* opb  = (const float*)d_in[9];
    const float* npw  = (const float*)d_in[12];
    const float* npow = (const float*)d_in[13];
    float* xbuf = (float*)d_out;

    float *p_ws, *p_xm, *p_t, *p_kv;
    cudaGetSymbolAddress((void**)&p_ws, g_ws);
    cudaGetSymbolAddress((void**)&p_xm, g_xm);
    cudaGetSymbolAddress((void**)&p_t,  g_t);
    cudaGetSymbolAddress((void**)&p_kv, g_kv);

    const int SMEM_E1 = 2 * (16384 + 64 * 128);    // 49152
    const int SMEM_E2 = 2 * (16384 + 128 * 128);   // 65536
    cudaFuncSetAttribute((const void*)k_mmh<0>, cudaFuncAttributeMaxDynamicSharedMemorySize, SMEM_E2);
    cudaFuncSetAttribute((const void*)k_mmh<1>, cudaFuncAttributeMaxDynamicSharedMemorySize, SMEM_E1);

    k_init_x<<<BB*LL, 256>>>(x_in, xbuf);
    k_init_ws<<<BB*SS*DD/256, 256>>>(ws_in);
    k_cw<<<SS*DD/256, 256>>>(cw, npw);

    for (int blk = 0; blk < 2; ++blk) {
        k_compete<<<BB*LL/16, 256>>>(xbuf, cb);
        k_topk_xm<<<BB*SS, 256>>>(xbuf);
        k_sgp<<<dim3(DD/64, 4), 256>>>(p_xm, ww, DD);
        k_sgr<<<64*DD/256, 256>>>(wb, p_ws, p_t, DD);
        k_rmsn<0><<<BB*SS, 256>>>(xbuf, npow);
        k_sgp<<<dim3(2*DD/64, 4), 256>>>(p_ws, ipw + (size_t)DD*DD, 2*DD);
        k_sgr<<<64*2*DD/256, 256>>>(ipb + DD, nullptr, p_kv, 2*DD);
        k_c<<<BB*HH*SS/256, 256>>>(ipb);
        k_m<<<dim3(DD/64, HH), 256>>>(ipw);
        k_p<<<dim3(DD/64, HH), 256>>>(opw);
        k_mmh<1><<<dim3(LL/128, HS/64, BB), 256, SMEM_E1>>>(nullptr, nullptr);
        k_mmh<0><<<dim3(LL/128, DD/128, BB), 256, SMEM_E2>>>(xbuf, opb);
        k_rmsn<1><<<BB*LL, 256>>>(xbuf, npow);
    }
}